// round 17
// baseline (speedup 1.0000x reference)
#include <cuda_runtime.h>
#include <math.h>

#define BOUND 10.0f
#define LN2F  0.6931471805599453f
#define EPSF  1e-6f
#define MIN_SCALE 1e-4f

#define MAXD 1024
#define K64  64
#define CELLS 512
// cell index computed from z2 = log2(u/(1-u)):  c = trunc(z2 * CPU2 + 256)
#define CPU2  (512.0f * LN2F / 20.0f)     // cells per log2-unit = 17.7446
#define CELLW (20.0f / 512.0f)            // cell width in z (natural-log) domain

// Precomputed packed spline tables (scratch; allocation-free per harness rules)
__device__ float4 g_P0[MAXD * K64];       // {x0/ln2, ln2/w, scale*y0+bias, scale*h}
__device__ float2 g_P1[MAXD * K64];       // {d0*w/h, (d0+d1)*w/h - 2}
__device__ unsigned int g_tab[MAXD * (CELLS / 4)];  // packed u8 lower-bound idx per cell
__device__ float g_scale[MAXD];
__device__ float g_bias[MAXD];

__device__ __forceinline__ float softplusf(float x) {
    return (x > 20.0f) ? x : log1pf(__expf(x));
}

// Warp-per-dim preproc: 8 dims/block (256 thr), shfl-only softmax + scan.
// Lane L owns entries L and L+32 of each K=64 vector.
#define PRE_DIMS 8
__global__ void __launch_bounds__(256)
spline_preproc_kernel(const float* __restrict__ raw_w,
                      const float* __restrict__ raw_h,
                      const float* __restrict__ raw_s,
                      const float* __restrict__ log_scale,
                      const float* __restrict__ bias) {
    const int warp = threadIdx.x >> 5, lane = threadIdx.x & 31;
    const int d = blockIdx.x * PRE_DIMS + warp;

    __shared__ float xs_s[PRE_DIMS][K64 + 1];
    __shared__ float ys_s[PRE_DIMS][K64 + 1];
    __shared__ float sl_s[PRE_DIMS][K64 + 1];
    float* xs = xs_s[warp];
    float* ys = ys_s[warp];
    float* sl = sl_s[warp];

    // ---- widths: softmax * 2B ----
    float w0 = raw_w[d * K64 + lane], w1 = raw_w[d * K64 + 32 + lane];
    float m = fmaxf(w0, w1);
    #pragma unroll
    for (int off = 16; off > 0; off >>= 1) m = fmaxf(m, __shfl_xor_sync(0xffffffffu, m, off));
    float e0 = __expf(w0 - m), e1 = __expf(w1 - m);
    float es = e0 + e1;
    #pragma unroll
    for (int off = 16; off > 0; off >>= 1) es += __shfl_xor_sync(0xffffffffu, es, off);
    float norm = (2.0f * BOUND) / es;
    float ww0 = e0 * norm, ww1 = e1 * norm;

    // ---- heights: softmax * 2B ----
    float h0 = raw_h[d * K64 + lane], h1 = raw_h[d * K64 + 32 + lane];
    float mh = fmaxf(h0, h1);
    #pragma unroll
    for (int off = 16; off > 0; off >>= 1) mh = fmaxf(mh, __shfl_xor_sync(0xffffffffu, mh, off));
    float f0 = __expf(h0 - mh), f1 = __expf(h1 - mh);
    float fs = f0 + f1;
    #pragma unroll
    for (int off = 16; off > 0; off >>= 1) fs += __shfl_xor_sync(0xffffffffu, fs, off);
    float normh = (2.0f * BOUND) / fs;
    float hh0 = f0 * normh, hh1 = f1 * normh;

    // ---- inclusive scans (two half-vectors in parallel) ----
    float sa = ww0, sb = ww1, sc = hh0, sd = hh1;
    #pragma unroll
    for (int off = 1; off < 32; off <<= 1) {
        float ta = __shfl_up_sync(0xffffffffu, sa, off);
        float tb = __shfl_up_sync(0xffffffffu, sb, off);
        float tc = __shfl_up_sync(0xffffffffu, sc, off);
        float td = __shfl_up_sync(0xffffffffu, sd, off);
        if (lane >= off) { sa += ta; sb += tb; sc += tc; sd += td; }
    }
    const float Aw = __shfl_sync(0xffffffffu, sa, 31);
    const float Ah = __shfl_sync(0xffffffffu, sc, 31);

    xs[lane + 1]  = sa - BOUND;
    xs[lane + 33] = (Aw + sb) - BOUND;
    ys[lane + 1]  = sc - BOUND;
    ys[lane + 33] = (Ah + sd) - BOUND;
    if (lane == 0) { xs[0] = -BOUND; ys[0] = -BOUND; }

    // ---- slopes ----
    sl[lane]      = softplusf(raw_s[d * (K64 + 1) + lane]);
    sl[lane + 32] = softplusf(raw_s[d * (K64 + 1) + 32 + lane]);
    float scale_d;
    if (lane == 0) {
        sl[K64] = softplusf(raw_s[d * (K64 + 1) + K64]);
        g_scale[d] = softplusf(log_scale[d]) + MIN_SCALE;
        g_bias[d] = bias[d];
    }
    __syncwarp();
    scale_d = softplusf(log_scale[d]) + MIN_SCALE;    // recompute in all lanes (cheap)
    const float bias_d = bias[d];

    // ---- pack per-interval params (t = lane, lane+32) ----
    // P0 = {x0/ln2, ln2/w, scale*y0+bias, scale*h}
    // P1 = {d0*w/h, (d0+d1)*w/h - 2}
    {
        int t = lane;
        float woh = ww0 / hh0;
        g_P0[d * K64 + t] = make_float4(xs[t] * (1.0f / LN2F), LN2F / ww0,
                                        fmaf(scale_d, ys[t], bias_d), scale_d * hh0);
        g_P1[d * K64 + t] = make_float2(sl[t] * woh,
                                        fmaf(sl[t] + sl[t + 1], woh, -2.0f));
        t = lane + 32;
        woh = ww1 / hh1;
        g_P0[d * K64 + t] = make_float4(xs[t] * (1.0f / LN2F), LN2F / ww1,
                                        fmaf(scale_d, ys[t], bias_d), scale_d * hh1);
        g_P1[d * K64 + t] = make_float2(sl[t] * woh,
                                        fmaf(sl[t] + sl[t + 1], woh, -2.0f));
    }

    // ---- cell table: 16 cells per lane (CELLS=512), built in z (natural-log)
    // domain; identical cell edges to the z2-domain grid used by the main
    // kernel (c-th edge = -10 + c*CELLW).  -1e-4 margin keeps the entry a
    // valid lower bound under fp rounding of the cell index.
    {
        #pragma unroll
        for (int q = 0; q < 4; q++) {
            unsigned int packed = 0;
            #pragma unroll
            for (int j = 0; j < 4; j++) {
                const int c = lane * 16 + q * 4 + j;
                const float left = fmaf((float)c, CELLW, -BOUND - 1e-4f);
                int idx = 0;
                #pragma unroll
                for (int st = 32; st > 0; st >>= 1) {
                    int cand = idx + st;
                    if (cand <= K64 - 1 && xs[cand] <= left) idx = cand;
                }
                packed |= ((unsigned int)idx) << (8 * j);
            }
            g_tab[d * (CELLS / 4) + lane * 4 + q] = packed;
        }
    }
}

// Main kernel: DTILE=16 dims/block; each thread owns 4 consecutive dims
// (float4 chunk of u/out); rgrp = tid>>2 -> 64 rows/block-iter; software-
// pipelined u/tau prefetch; additive smem swizzle (slot (k + dim>>2)&63)
// keeps LDS phases conflict-free.
// All spline math in log2 domain with s-normalized slopes + folded epilogue:
//   z2 = log2(u/(1-u));  theta = (z2 - x02)*invw2;  t1m = theta(1-theta)
//   frac = (theta^2 + d0'*t1m) / (1 + dsum'*t1m)
//   out  = tau * (ys0 + hs*frac)       [scale & bias pre-folded into ys0/hs]
#define DTILE 16
#define TPB   256
#define STRD  65           // padded per-dim stride (entries)
#define TABSTRD 516        // padded tab stride (bytes)
#define GRIDY 11           // 64*11=704 blocks (best-measured config)
#define B2LO (-BOUND / LN2F)
#define B2HI ( BOUND / LN2F)

__global__ void __launch_bounds__(TPB)
rqs_main_kernel(const float* __restrict__ u,
                const float* __restrict__ tau,
                float* __restrict__ out,
                int B, int D) {
    __shared__ float4 sP0[DTILE * STRD];            // 16640 B
    __shared__ float2 sP1[DTILE * STRD];            //  8320 B
    __shared__ float  sXK[DTILE * STRD];            //  4160 B (x0/ln2)
    __shared__ unsigned char sTab[DTILE * TABSTRD]; //  8256 B
    __shared__ float sScale[DTILE], sBias[DTILE];   // rare outside path only

    const int d0 = blockIdx.x * DTILE;

    for (int i = threadIdx.x; i < DTILE * K64; i += TPB) {
        const int dim = i >> 6, k = i & 63;
        const int kp = (k + (dim >> 2)) & 63;
        const float4 p = g_P0[d0 * K64 + i];
        sP0[dim * STRD + kp] = p;
        sXK[dim * STRD + kp] = p.x;                 // x0 in log2 domain
        sP1[dim * STRD + kp] = g_P1[d0 * K64 + i];
    }
    for (int i = threadIdx.x; i < DTILE * (CELLS / 4); i += TPB) {
        const int dim = i >> 7, j = i & 127;
        *(unsigned int*)(sTab + dim * TABSTRD + 4 * j) = g_tab[d0 * (CELLS / 4) + i];
    }
    if (threadIdx.x < DTILE) {
        sScale[threadIdx.x] = g_scale[d0 + threadIdx.x];
        sBias[threadIdx.x]  = g_bias[d0 + threadIdx.x];
    }
    __syncthreads();

    const int laned = threadIdx.x & 3;
    const int rgrp  = threadIdx.x >> 2;
    const int dbase = 4 * laned;

    const int rowsPerIter = TPB / 4;                 // 64
    const int rstride = gridDim.y * rowsPerIter;

    int r = blockIdx.y * rowsPerIter + rgrp;

    float4 u4 = make_float4(0.f, 0.f, 0.f, 0.f);
    float tv = 0.f;
    if (r < B) {
        u4 = *(const float4*)(u + (size_t)r * D + d0 + dbase);
        tv = __ldg(tau + r);
    }

    while (r < B) {
        const int rn = r + rstride;
        float4 u4n;
        float tvn;
        if (rn < B) {
            u4n = *(const float4*)(u + (size_t)rn * D + d0 + dbase);
            tvn = __ldg(tau + rn);
        }

        // z2 = log2(u/(1-u)) — single MUFU.LG2 + RCP path, no ln2 multiply
        float zz[4];
        {
            const float ua[4] = {u4.x, u4.y, u4.z, u4.w};
            #pragma unroll
            for (int jj = 0; jj < 4; jj++) {
                const float us = fminf(fmaxf(ua[jj], EPSF), 1.0f - EPSF);
                zz[jj] = __log2f(__fdividef(us, 1.0f - us));
            }
        }

        int idx[4];
        #pragma unroll
        for (int jj = 0; jj < 4; jj++) {
            int c = (int)fmaf(zz[jj], CPU2, (float)(CELLS / 2));
            c = max(0, min(CELLS - 1, c));
            idx[jj] = sTab[(dbase + jj) * TABSTRD + c];
        }

        #pragma unroll
        for (int jj = 0; jj < 4; jj++) {
            const float* xs = sXK + (dbase + jj) * STRD;
            int nxt = idx[jj] + 1;
            while (nxt < K64 && xs[(nxt + laned) & 63] <= zz[jj]) { idx[jj] = nxt; ++nxt; }
        }

        float res[4];
        #pragma unroll
        for (int jj = 0; jj < 4; jj++) {
            const float z2 = zz[jj];
            if (z2 > B2LO && z2 < B2HI) {
                const int kp = (idx[jj] + laned) & 63;
                const float4 p = sP0[(dbase + jj) * STRD + kp];  // {x02,invw2,ys0,hs}
                const float2 q = sP1[(dbase + jj) * STRD + kp];  // {d0', dsum'}
                const float theta = (z2 - p.x) * p.y;
                const float t1m = theta * (1.0f - theta);
                const float num = fmaf(q.x, t1m, theta * theta);
                const float den = fmaf(q.y, t1m, 1.0f);
                res[jj] = fmaf(p.w, __fdividef(num, den), p.z);
            } else {
                // rare (~1e-4): identity through spline, then scale+bias
                const float z = z2 * LN2F;
                res[jj] = fmaf(z, sScale[dbase + jj], sBias[dbase + jj]);
            }
        }

        float4 o4;
        o4.x = tv * res[0];
        o4.y = tv * res[1];
        o4.z = tv * res[2];
        o4.w = tv * res[3];
        *(float4*)(out + (size_t)r * D + d0 + dbase) = o4;

        u4 = u4n;
        tv = tvn;
        r = rn;
    }
}

extern "C" void kernel_launch(void* const* d_in, const int* in_sizes, int n_in,
                              void* d_out, int out_size) {
    const float* u         = (const float*)d_in[0];
    const float* tau       = (const float*)d_in[1];
    const float* log_scale = (const float*)d_in[2];
    const float* bias      = (const float*)d_in[3];
    const float* raw_w     = (const float*)d_in[4];
    const float* raw_h     = (const float*)d_in[5];
    const float* raw_s     = (const float*)d_in[6];
    float* out = (float*)d_out;

    const int D = in_sizes[2];
    const int B = in_sizes[0] / D;

    spline_preproc_kernel<<<D / PRE_DIMS, 256>>>(raw_w, raw_h, raw_s, log_scale, bias);

    dim3 grid(D / DTILE, GRIDY);
    rqs_main_kernel<<<grid, TPB>>>(u, tau, out, B, D);
}